// round 3
// baseline (speedup 1.0000x reference)
#include <cuda_runtime.h>
#include <cuda_fp16.h>

// QConv2d: 3x3 conv, B=16, C=32, N=64, H=W=56, stride 1, pad 1.
// Bit-exact emulation of per-k fp16 (E5M10) requantized accumulation:
//   p   = fp16(fp32(a * w))  -> mul.rn.f32x2 (2 n-lanes) + cvt.rn.f16x2.f32
//   acc = fp16(acc + p)      -> HADD2 (== fp16(fp32 add), innocuous dbl rounding)
// k order = c*9 + i*3 + j, matching lax.scan order in the reference.
//
// R3: f32x2 multiplies with register-MOV lane duplication (no smem dup),
// so smem stays at 96768 B -> 2 CTAs/SM / 28 warps (R1 occupancy) while
// cutting instr/MAC from 2.375 to ~1.96.

#define TB 448
typedef unsigned long long ull;

#define ROWP 60                           // padded input row (floats), 16B-aligned
#define SIN_FLOATS (32 * 3 * ROWP)        // 5760
#define SW_FLOATS  (288 * 64)             // 18432
#define SMEM_BYTES ((SIN_FLOATS + SW_FLOATS) * 4)   // 96768

__device__ __forceinline__ ull dup2(float v) {
    ull d;
    asm("mov.b64 %0, {%1, %1};" : "=l"(d) : "f"(v));
    return d;
}
__device__ __forceinline__ ull mul2_rn(ull a, ull b) {
    ull d;
    asm("mul.rn.f32x2 %0, %1, %2;" : "=l"(d) : "l"(a), "l"(b));
    return d;
}
__device__ __forceinline__ __half2 cvt_pair(ull p) {
    unsigned lo, hi, h;
    asm("mov.b64 {%0, %1}, %2;" : "=r"(lo), "=r"(hi) : "l"(p));
    // cvt.rn.f16x2.f32 d, a, b : a -> upper half, b -> lower half
    asm("cvt.rn.f16x2.f32 %0, %1, %2;" : "=r"(h) : "r"(hi), "r"(lo));
    return *reinterpret_cast<__half2*>(&h);
}

__global__ void __launch_bounds__(TB, 2) qconv2d_kernel(
    const float* __restrict__ x,      // [16][32][56][56]
    const float* __restrict__ w,      // [64][32][3][3] = [64][288]
    const float* __restrict__ bias,   // [64]
    float* __restrict__ out)          // [16][64][56][56]
{
    extern __shared__ float sm[];
    float* sin = sm;                      // [c][r(3)][ROWP]
    float* sw  = sm + SIN_FLOATS;         // [k=288][n=64], fp16-valued fp32

    const int y0  = blockIdx.x;   // output row 0..55
    const int b   = blockIdx.y;   // batch 0..15
    const int tid = threadIdx.x;

    // ---- weights: coalesced gmem read, transpose to [k][n], quantize ----
    for (int idx = tid; idx < 64 * 288; idx += TB) {
        int n = idx / 288;
        int k = idx % 288;
        sw[k * 64 + n] = __half2float(__float2half_rn(w[idx]));
    }

    // ---- input rows y0-1..y0+1, 32 ch, padded row of 60 (x offset by 1) ----
    const float* xb = x + (size_t)b * 32 * 56 * 56;
    for (int idx = tid; idx < SIN_FLOATS; idx += TB) {
        int c   = idx / (3 * ROWP);
        int r3  = idx % (3 * ROWP);
        int r   = r3 / ROWP;
        int xs  = r3 % ROWP;
        int yg  = y0 - 1 + r;
        int xg  = xs - 1;
        float v = 0.0f;
        if (yg >= 0 && yg < 56 && xg >= 0 && xg < 56)
            v = xb[(c * 56 + yg) * 56 + xg];
        sin[idx] = v;
    }
    __syncthreads();

    const int tn = tid & 31;      // n-pair: n0 = 2*tn, n1 = 2*tn+1
    const int g  = tid >> 5;      // pixel group 0..13
    const int x0 = g * 4;

    __half2 acc0 = __float2half2_rn(0.0f);
    __half2 acc1 = acc0, acc2 = acc0, acc3 = acc0;

    const float* swt = sw + 2 * tn;
    const float* ab  = sin + x0;          // 16B aligned (x0 % 4 == 0, ROWP % 4 == 0)

    #pragma unroll 1
    for (int c = 0; c < 32; ++c) {
        #pragma unroll
        for (int i = 0; i < 3; ++i) {
            const float* ar = ab + (c * 3 + i) * ROWP;
            float4 a03 = *reinterpret_cast<const float4*>(ar);       // a0..a3 (LDS.128)
            float2 a45 = *reinterpret_cast<const float2*>(ar + 4);   // a4,a5  (LDS.64)
            ull d0 = dup2(a03.x), d1 = dup2(a03.y), d2 = dup2(a03.z);
            ull d3 = dup2(a03.w), d4 = dup2(a45.x), d5 = dup2(a45.y);

            const float* wr = swt + (c * 9 + i * 3) * 64;
            ull w0 = *reinterpret_cast<const ull*>(wr);
            ull w1 = *reinterpret_cast<const ull*>(wr + 64);
            ull w2 = *reinterpret_cast<const ull*>(wr + 128);

            // j = 0
            acc0 = __hadd2(acc0, cvt_pair(mul2_rn(d0, w0)));
            acc1 = __hadd2(acc1, cvt_pair(mul2_rn(d1, w0)));
            acc2 = __hadd2(acc2, cvt_pair(mul2_rn(d2, w0)));
            acc3 = __hadd2(acc3, cvt_pair(mul2_rn(d3, w0)));
            // j = 1
            acc0 = __hadd2(acc0, cvt_pair(mul2_rn(d1, w1)));
            acc1 = __hadd2(acc1, cvt_pair(mul2_rn(d2, w1)));
            acc2 = __hadd2(acc2, cvt_pair(mul2_rn(d3, w1)));
            acc3 = __hadd2(acc3, cvt_pair(mul2_rn(d4, w1)));
            // j = 2
            acc0 = __hadd2(acc0, cvt_pair(mul2_rn(d2, w2)));
            acc1 = __hadd2(acc1, cvt_pair(mul2_rn(d3, w2)));
            acc2 = __hadd2(acc2, cvt_pair(mul2_rn(d4, w2)));
            acc3 = __hadd2(acc3, cvt_pair(mul2_rn(d5, w2)));
        }
    }

    // ---- epilogue: out = fp32(fp16(acc + fp16(bias))) ----
    const int n0 = 2 * tn;
    __half2 qb = __halves2half2(__float2half_rn(bias[n0]),
                                __float2half_rn(bias[n0 + 1]));

    __half2 r0 = __hadd2(acc0, qb);
    __half2 r1 = __hadd2(acc1, qb);
    __half2 r2 = __hadd2(acc2, qb);
    __half2 r3 = __hadd2(acc3, qb);

    float4 v0, v1;
    v0.x = __low2float(r0);  v0.y = __low2float(r1);
    v0.z = __low2float(r2);  v0.w = __low2float(r3);
    v1.x = __high2float(r0); v1.y = __high2float(r1);
    v1.z = __high2float(r2); v1.w = __high2float(r3);

    size_t o0 = (((size_t)b * 64 + n0) * 56 + y0) * 56 + x0;
    size_t o1 = (((size_t)b * 64 + n0 + 1) * 56 + y0) * 56 + x0;
    *reinterpret_cast<float4*>(out + o0) = v0;
    *reinterpret_cast<float4*>(out + o1) = v1;
}

extern "C" void kernel_launch(void* const* d_in, const int* in_sizes, int n_in,
                              void* d_out, int out_size)
{
    const float* x    = (const float*)d_in[0];
    const float* w    = (const float*)d_in[1];
    const float* bias = (const float*)d_in[2];
    float* out = (float*)d_out;

    cudaFuncSetAttribute(qconv2d_kernel,
                         cudaFuncAttributeMaxDynamicSharedMemorySize,
                         SMEM_BYTES);

    dim3 grid(56, 16);   // (output row, batch)
    qconv2d_kernel<<<grid, TB, SMEM_BYTES>>>(x, w, bias, out);
}